// round 3
// baseline (speedup 1.0000x reference)
#include <cuda_runtime.h>
#include <cuda_bf16.h>

#define NN 50000
#define NE 800000
#define NV 1000
#define F 128
#define NG 64
#define NC 10
#define NSCANBLK 49

typedef unsigned long long u64;

// ---- scratch (no allocations allowed) ----
__device__ float    g_tl[NV * F];       // embed_table @ Wl1^T (fp32, unused by gather now)
__device__ float    g_tr[NV * F];       // embed_table @ Wr1^T
__device__ unsigned g_tlh[NV * 64];     // tl in bf16 (2 feats per u32)
__device__ float    g_h1[NN * F];       // fp32 h1 (GEMM operand)
__device__ unsigned g_h1h[NN * 64];     // h1 in bf16 (gather payload)
__device__ float    g_agg[NN * F];
__device__ float    g_h2[NN * F];
__device__ float    g_pool[NG * F];
__device__ float    g_WT[256 * F];      // [Wl2 | Wr2] transposed: WT[k][j]
__device__ int      g_deg[NN];
__device__ int      g_off[NN + 1];
__device__ int      g_cur[NN];
__device__ int      g_csr[NE];          // src node id
__device__ int      g_csrv[NE];         // x_idx[src] (vocab id)
__device__ int      g_gcnt[NG];
__device__ int      g_goff[NG + 1];
__device__ int      g_psum[64];

__device__ __forceinline__ float bf_lo(unsigned u) { return __uint_as_float(u << 16); }
__device__ __forceinline__ float bf_hi(unsigned u) { return __uint_as_float(u & 0xFFFF0000u); }
__device__ __forceinline__ unsigned bfpack(float lo, float hi) {
    unsigned r;
    asm("cvt.rn.bf16x2.f32 %0, %1, %2;" : "=r"(r) : "f"(hi), "f"(lo));
    return r;
}
__device__ __forceinline__ u64 fdup(float f) {
    u64 r;
    asm("mov.b64 %0, {%1, %1};" : "=l"(r) : "f"(f));
    return r;
}

// ---------------- init ----------------
__global__ void k_init() {
    int i = blockIdx.x * blockDim.x + threadIdx.x;
    int stride = gridDim.x * blockDim.x;
    for (int x = i; x < NN; x += stride) g_deg[x] = 0;
    for (int x = i; x < NG; x += stride) g_gcnt[x] = 0;
}

// ---------------- degree & graph-size counts ----------------
__global__ void k_count(const int* __restrict__ dst, const int* __restrict__ batch) {
    int i = blockIdx.x * blockDim.x + threadIdx.x;
    int stride = gridDim.x * blockDim.x;
    for (int e = i; e < NE; e += stride) atomicAdd(&g_deg[dst[e]], 1);
    for (int n = i; n < NN; n += stride) atomicAdd(&g_gcnt[batch[n]], 1);
}

__device__ __forceinline__ int warp_incl_scan(int v) {
    int lane = threadIdx.x & 31;
#pragma unroll
    for (int d = 1; d < 32; d <<= 1) {
        int t = __shfl_up_sync(0xffffffffu, v, d);
        if (lane >= d) v += t;
    }
    return v;
}

__global__ void k_scan_blk() {
    __shared__ int wsum[32];
    int t = threadIdx.x, lane = t & 31, w = t >> 5;
    int i = blockIdx.x * 1024 + t;
    int v = (i < NN) ? g_deg[i] : 0;
    int incl = warp_incl_scan(v);
    if (lane == 31) wsum[w] = incl;
    __syncthreads();
    if (w == 0) wsum[lane] = warp_incl_scan(wsum[lane]);
    __syncthreads();
    int excl = (w ? wsum[w - 1] : 0) + incl - v;
    if (i < NN) g_off[i] = excl;
    if (t == 1023) g_psum[blockIdx.x] = wsum[31];
}

__global__ void k_scan_top() {
    int t = threadIdx.x, lane = t & 31;
    if (t < 32) {
        int carry = 0;
        for (int base = 0; base < NSCANBLK; base += 32) {
            int i = base + lane;
            int v = (i < NSCANBLK) ? g_psum[i] : 0;
            int incl = warp_incl_scan(v);
            if (i < NSCANBLK) g_psum[i] = carry + incl - v;
            carry += __shfl_sync(0xffffffffu, incl, 31);
        }
    } else {
        int carry = 0;
        for (int base = 0; base < NG; base += 32) {
            int i = base + lane;
            int v = g_gcnt[i];
            int incl = warp_incl_scan(v);
            g_goff[i] = carry + incl - v;
            carry += __shfl_sync(0xffffffffu, incl, 31);
        }
        if (lane == 0) g_goff[NG] = NN;
    }
}

__global__ void k_scan_add() {
    int t = threadIdx.x;
    int i = blockIdx.x * 1024 + t;
    if (i < NN) {
        int o = g_off[i] + g_psum[blockIdx.x];
        g_off[i] = o;
        g_cur[i] = o;
    }
    if (i == 0) g_off[NN] = NE;
}

// ---------------- CSR fill (resolve vocab id here) ----------------
__global__ void k_csr(const int* __restrict__ src, const int* __restrict__ dst,
                      const int* __restrict__ x_idx) {
    int i = blockIdx.x * blockDim.x + threadIdx.x;
    int stride = gridDim.x * blockDim.x;
    for (int e = i; e < NE; e += stride) {
        int s = src[e];
        int pos = atomicAdd(&g_cur[dst[e]], 1);
        g_csr[pos] = s;
        g_csrv[pos] = x_idx[s];
    }
}

// ---------------- transpose weights ----------------
__global__ void k_wt(const float* __restrict__ Wl2, const float* __restrict__ Wr2) {
    int idx = blockIdx.x * 256 + threadIdx.x;
    int k = idx >> 7, j = idx & 127;
    g_WT[idx] = (k < 128) ? Wl2[j * F + k] : Wr2[j * F + (k - 128)];
}

// ---------------- vocab-table dual GEMM: tl=E@Wl1^T (+bf16 copy), tr=E@Wr1^T ----------------
__global__ __launch_bounds__(256)
void k_gemm_pre(const float* __restrict__ in,
                const float* __restrict__ W1, const float* __restrict__ W2,
                float* __restrict__ out2, int rows) {
    __shared__ float sA[128 * 33];
    const int node0 = blockIdx.x * 32;
    const int t = threadIdx.x;
    for (int idx = t; idx < 32 * 128; idx += 256) {
        int n = idx >> 7, k = idx & 127;
        int g = node0 + n;
        sA[k * 33 + n] = (g < rows) ? in[g * F + k] : 0.f;
    }
    __syncthreads();
    const int lane = t & 31, w = t >> 5;
    const int j0 = w * 16;
    float acc1[16], acc2[16];
#pragma unroll
    for (int jj = 0; jj < 16; jj++) { acc1[jj] = 0.f; acc2[jj] = 0.f; }
#pragma unroll 2
    for (int k0 = 0; k0 < 128; k0 += 4) {
        float a0 = sA[(k0 + 0) * 33 + lane];
        float a1 = sA[(k0 + 1) * 33 + lane];
        float a2 = sA[(k0 + 2) * 33 + lane];
        float a3 = sA[(k0 + 3) * 33 + lane];
#pragma unroll
        for (int jj = 0; jj < 16; jj++) {
            const float4 w1 = *reinterpret_cast<const float4*>(&W1[(j0 + jj) * F + k0]);
            acc1[jj] = fmaf(a0, w1.x, fmaf(a1, w1.y, fmaf(a2, w1.z, fmaf(a3, w1.w, acc1[jj]))));
            const float4 w2 = *reinterpret_cast<const float4*>(&W2[(j0 + jj) * F + k0]);
            acc2[jj] = fmaf(a0, w2.x, fmaf(a1, w2.y, fmaf(a2, w2.z, fmaf(a3, w2.w, acc2[jj]))));
        }
    }
    const int node = node0 + lane;
    if (node < rows) {
#pragma unroll
        for (int jj = 0; jj < 16; jj += 2)
            g_tlh[node * 64 + (j0 + jj) / 2] = bfpack(acc1[jj], acc1[jj + 1]);
#pragma unroll
        for (int jj = 0; jj < 16; jj++)
            out2[node * F + j0 + jj] = acc2[jj];
    }
}

// ---------------- layer-1: h1 = relu(mean(tl_bf16[csrv]) + bl1 + tr[x_idx[n]]) ----------------
__global__ void k_agg1(const int* __restrict__ x_idx, const float* __restrict__ bl1) {
    int gid = blockIdx.x * blockDim.x + threadIdx.x;
    int n = gid >> 5;
    int lane = gid & 31;
    if (n >= NN) return;
    int o0 = g_off[n], o1 = g_off[n + 1];
    const uint2* tl2 = reinterpret_cast<const uint2*>(g_tlh);
    float4 acc = make_float4(0.f, 0.f, 0.f, 0.f);
    int e = o0;
    for (; e + 3 < o1; e += 4) {
        uint2 q0 = tl2[g_csrv[e] * 32 + lane];
        uint2 q1 = tl2[g_csrv[e + 1] * 32 + lane];
        uint2 q2 = tl2[g_csrv[e + 2] * 32 + lane];
        uint2 q3 = tl2[g_csrv[e + 3] * 32 + lane];
        acc.x += (bf_lo(q0.x) + bf_lo(q1.x)) + (bf_lo(q2.x) + bf_lo(q3.x));
        acc.y += (bf_hi(q0.x) + bf_hi(q1.x)) + (bf_hi(q2.x) + bf_hi(q3.x));
        acc.z += (bf_lo(q0.y) + bf_lo(q1.y)) + (bf_lo(q2.y) + bf_lo(q3.y));
        acc.w += (bf_hi(q0.y) + bf_hi(q1.y)) + (bf_hi(q2.y) + bf_hi(q3.y));
    }
    for (; e < o1; e++) {
        uint2 q0 = tl2[g_csrv[e] * 32 + lane];
        acc.x += bf_lo(q0.x); acc.y += bf_hi(q0.x);
        acc.z += bf_lo(q0.y); acc.w += bf_hi(q0.y);
    }
    float inv = 1.f / fmaxf((float)(o1 - o0), 1.f);
    int vs = x_idx[n];
    float4 r = reinterpret_cast<const float4*>(g_tr)[vs * 32 + lane];
    float4 b = reinterpret_cast<const float4*>(bl1)[lane];
    float4 h;
    h.x = fmaxf(fmaf(acc.x, inv, b.x + r.x), 0.f);
    h.y = fmaxf(fmaf(acc.y, inv, b.y + r.y), 0.f);
    h.z = fmaxf(fmaf(acc.z, inv, b.z + r.z), 0.f);
    h.w = fmaxf(fmaf(acc.w, inv, b.w + r.w), 0.f);
    reinterpret_cast<float4*>(g_h1)[n * 32 + lane] = h;
    uint2 hb;
    hb.x = bfpack(h.x, h.y);
    hb.y = bfpack(h.z, h.w);
    reinterpret_cast<uint2*>(g_h1h)[n * 32 + lane] = hb;
}

// ---------------- layer-2 aggregate from bf16 h1 ----------------
__global__ void k_agg2() {
    int gid = blockIdx.x * blockDim.x + threadIdx.x;
    int n = gid >> 5;
    int lane = gid & 31;
    if (n >= NN) return;
    int o0 = g_off[n], o1 = g_off[n + 1];
    const uint2* h2v = reinterpret_cast<const uint2*>(g_h1h);
    float4 acc = make_float4(0.f, 0.f, 0.f, 0.f);
    int e = o0;
    for (; e + 3 < o1; e += 4) {
        uint2 q0 = h2v[g_csr[e] * 32 + lane];
        uint2 q1 = h2v[g_csr[e + 1] * 32 + lane];
        uint2 q2 = h2v[g_csr[e + 2] * 32 + lane];
        uint2 q3 = h2v[g_csr[e + 3] * 32 + lane];
        acc.x += (bf_lo(q0.x) + bf_lo(q1.x)) + (bf_lo(q2.x) + bf_lo(q3.x));
        acc.y += (bf_hi(q0.x) + bf_hi(q1.x)) + (bf_hi(q2.x) + bf_hi(q3.x));
        acc.z += (bf_lo(q0.y) + bf_lo(q1.y)) + (bf_lo(q2.y) + bf_lo(q3.y));
        acc.w += (bf_hi(q0.y) + bf_hi(q1.y)) + (bf_hi(q2.y) + bf_hi(q3.y));
    }
    for (; e < o1; e++) {
        uint2 q0 = h2v[g_csr[e] * 32 + lane];
        acc.x += bf_lo(q0.x); acc.y += bf_hi(q0.x);
        acc.z += bf_lo(q0.y); acc.w += bf_hi(q0.y);
    }
    float inv = 1.f / fmaxf((float)(o1 - o0), 1.f);
    float4 o;
    o.x = acc.x * inv; o.y = acc.y * inv; o.z = acc.z * inv; o.w = acc.w * inv;
    reinterpret_cast<float4*>(g_agg)[n * 32 + lane] = o;
}

// ---------------- main GEMM via packed fma.rn.f32x2 ----------------
// h2 = relu([agg|h1] @ WT + bl2). M=NN, N=128, K=256. BM=128, BN=128, BK=8.
__global__ __launch_bounds__(256, 2)
void k_gemm2(const float* __restrict__ A1, const float* __restrict__ A2,
             const float* __restrict__ bias, float* __restrict__ out) {
    __shared__ u64   sAd[8][128];   // duplicated A: (a,a) pairs
    __shared__ float sBf[8][128];   // natural B rows
    const int t = threadIdx.x;
    const int node0 = blockIdx.x * 128;
    const int tx = t & 15, ty = t >> 4;

    u64 acc[8][4];
#pragma unroll
    for (int i = 0; i < 8; i++)
#pragma unroll
        for (int j = 0; j < 4; j++) acc[i][j] = 0ULL;

    const int ar = t >> 1;              // node row within tile
    const int akq = (t & 1) * 4;        // k quad within BK
    const int an = node0 + ar;
    const bool avalid = an < NN;
    const int bk = t >> 5;              // WT k row (0..7)
    const int bj = (t * 4) & 127;       // WT j quad

    float4 av = make_float4(0.f, 0.f, 0.f, 0.f);
    if (avalid) av = *reinterpret_cast<const float4*>(&A1[an * F + akq]);
    float4 wv = *reinterpret_cast<const float4*>(&g_WT[bk * F + bj]);

    for (int k0 = 0; k0 < 256; k0 += 8) {
        sAd[akq + 0][ar] = fdup(av.x);
        sAd[akq + 1][ar] = fdup(av.y);
        sAd[akq + 2][ar] = fdup(av.z);
        sAd[akq + 3][ar] = fdup(av.w);
        *reinterpret_cast<float4*>(&sBf[bk][bj]) = wv;
        __syncthreads();

        if (k0 + 8 < 256) {  // prefetch next chunk
            const float* Asrc = (k0 + 8 < 128) ? A1 : A2;
            int kk = ((k0 + 8) & 127) + akq;
            if (avalid) av = *reinterpret_cast<const float4*>(&Asrc[an * F + kk]);
            wv = *reinterpret_cast<const float4*>(&g_WT[(k0 + 8 + bk) * F + bj]);
        }

#pragma unroll
        for (int kk2 = 0; kk2 < 8; kk2++) {
            ulonglong2 a01 = *reinterpret_cast<ulonglong2*>(&sAd[kk2][ty * 8]);
            ulonglong2 a23 = *reinterpret_cast<ulonglong2*>(&sAd[kk2][ty * 8 + 2]);
            ulonglong2 a45 = *reinterpret_cast<ulonglong2*>(&sAd[kk2][ty * 8 + 4]);
            ulonglong2 a67 = *reinterpret_cast<ulonglong2*>(&sAd[kk2][ty * 8 + 6]);
            ulonglong2 b01 = *reinterpret_cast<ulonglong2*>(&sBf[kk2][tx * 8]);
            ulonglong2 b23 = *reinterpret_cast<ulonglong2*>(&sBf[kk2][tx * 8 + 4]);
            u64 ap[8] = {a01.x, a01.y, a23.x, a23.y, a45.x, a45.y, a67.x, a67.y};
            u64 bp[4] = {b01.x, b01.y, b23.x, b23.y};
#pragma unroll
            for (int i = 0; i < 8; i++)
#pragma unroll
                for (int j = 0; j < 4; j++)
                    asm("fma.rn.f32x2 %0, %1, %2, %0;"
                        : "+l"(acc[i][j]) : "l"(ap[i]), "l"(bp[j]));
        }
        __syncthreads();
    }

    float bj8[8];
    *(float4*)&bj8[0] = *(const float4*)&bias[tx * 8];
    *(float4*)&bj8[4] = *(const float4*)&bias[tx * 8 + 4];
#pragma unroll
    for (int i = 0; i < 8; i++) {
        int n = node0 + ty * 8 + i;
        if (n < NN) {
            float v[8];
#pragma unroll
            for (int j = 0; j < 4; j++)
                asm("mov.b64 {%0, %1}, %2;" : "=f"(v[2 * j]), "=f"(v[2 * j + 1]) : "l"(acc[i][j]));
            float4 o0, o1;
            o0.x = fmaxf(v[0] + bj8[0], 0.f);
            o0.y = fmaxf(v[1] + bj8[1], 0.f);
            o0.z = fmaxf(v[2] + bj8[2], 0.f);
            o0.w = fmaxf(v[3] + bj8[3], 0.f);
            o1.x = fmaxf(v[4] + bj8[4], 0.f);
            o1.y = fmaxf(v[5] + bj8[5], 0.f);
            o1.z = fmaxf(v[6] + bj8[6], 0.f);
            o1.w = fmaxf(v[7] + bj8[7], 0.f);
            *reinterpret_cast<float4*>(&out[n * F + tx * 8]) = o0;
            *reinterpret_cast<float4*>(&out[n * F + tx * 8 + 4]) = o1;
        }
    }
}

// ---------------- per-graph mean pool ----------------
__global__ void k_pool2() {
    __shared__ float4 red[8][32];
    int g = blockIdx.x;
    int s = g_goff[g], e = g_goff[g + 1];
    int lane = threadIdx.x & 31, w = threadIdx.x >> 5;
    const float4* h4 = reinterpret_cast<const float4*>(g_h2);
    float4 acc = make_float4(0.f, 0.f, 0.f, 0.f);
    for (int n = s + w; n < e; n += 8) {
        float4 v = h4[n * 32 + lane];
        acc.x += v.x; acc.y += v.y; acc.z += v.z; acc.w += v.w;
    }
    red[w][lane] = acc;
    __syncthreads();
    if (w == 0) {
        float4 a = red[0][lane];
#pragma unroll
        for (int i = 1; i < 8; i++) {
            float4 b = red[i][lane];
            a.x += b.x; a.y += b.y; a.z += b.z; a.w += b.w;
        }
        float inv = 1.f / fmaxf((float)(e - s), 1.f);
        a.x *= inv; a.y *= inv; a.z *= inv; a.w *= inv;
        reinterpret_cast<float4*>(g_pool)[g * 32 + lane] = a;
    }
}

// ---------------- classifier ----------------
__global__ void k_out(const float* __restrict__ linW, const float* __restrict__ linb,
                      float* __restrict__ out) {
    int g = blockIdx.x;
    int c = threadIdx.x >> 5;
    int lane = threadIdx.x & 31;
    if (c >= NC) return;
    float s = 0.f;
    for (int k = lane; k < F; k += 32)
        s += g_pool[g * F + k] * linW[c * F + k];
#pragma unroll
    for (int d = 16; d > 0; d >>= 1) s += __shfl_down_sync(0xffffffffu, s, d);
    if (lane == 0) out[g * NC + c] = s + linb[c];
}

extern "C" void kernel_launch(void* const* d_in, const int* in_sizes, int n_in,
                              void* d_out, int out_size) {
    const int*   x_idx = (const int*)d_in[0];
    const int*   eidx  = (const int*)d_in[1];
    const int*   batch = (const int*)d_in[2];
    const float* table = (const float*)d_in[3];
    const float* Wl1   = (const float*)d_in[4];
    const float* bl1   = (const float*)d_in[5];
    const float* Wr1   = (const float*)d_in[6];
    const float* Wl2   = (const float*)d_in[7];
    const float* bl2   = (const float*)d_in[8];
    const float* Wr2   = (const float*)d_in[9];
    const float* linW  = (const float*)d_in[10];
    const float* linb  = (const float*)d_in[11];
    float* out = (float*)d_out;

    const int* src = eidx;
    const int* dst = eidx + NE;

    float *d_tr, *d_h1, *d_agg, *d_h2;
    cudaGetSymbolAddress((void**)&d_tr, g_tr);
    cudaGetSymbolAddress((void**)&d_h1, g_h1);
    cudaGetSymbolAddress((void**)&d_agg, g_agg);
    cudaGetSymbolAddress((void**)&d_h2, g_h2);

    k_init<<<196, 256>>>();
    k_count<<<3125, 256>>>(dst, batch);
    k_scan_blk<<<NSCANBLK, 1024>>>();
    k_scan_top<<<1, 64>>>();
    k_scan_add<<<NSCANBLK, 1024>>>();
    k_csr<<<3125, 256>>>(src, dst, x_idx);

    // weight prep
    k_wt<<<128, 256>>>(Wl2, Wr2);
    k_gemm_pre<<<(NV + 31) / 32, 256>>>(table, Wl1, Wr1, d_tr, NV);

    // layer 1
    k_agg1<<<(NN * 32 + 255) / 256, 256>>>(x_idx, bl1);

    // layer 2
    k_agg2<<<(NN * 32 + 255) / 256, 256>>>();
    k_gemm2<<<(NN + 127) / 128, 256>>>(d_agg, d_h1, bl2, d_h2);

    // pool + classify
    k_pool2<<<NG, 256>>>();
    k_out<<<NG, 320>>>(linW, linb, out);
}